// round 1
// baseline (speedup 1.0000x reference)
#include <cuda_runtime.h>
#include <math.h>
#include <stdint.h>

#define B 2
#define D 128
#define P 3600
#define NN 57600
#define C 19
#define GAMMA 0.75f
#define EPS 1e-8f

#define TP 64
#define TN 64
#define NSPLIT 4
#define NTILES_PER_CHUNK (NN / TN / NSPLIT)   // 900/4 = 225

// -------- scratch (device globals; no allocation allowed) --------
__device__ __align__(16) int   g_neg_labels[B * NN];
__device__ __align__(16) int   g_labels1[B * P];
__device__ __align__(16) float g_mask1[B * P];
__device__ __align__(16) float g_pos1[B * P];     // already scaled by 1/TEMP
__device__ __align__(16) float g_negsum[B * P];

// -------- zero accumulators (graph replays must be deterministic) --------
__global__ void k_zero() {
    int i = blockIdx.x * blockDim.x + threadIdx.x;
    if (i < B * P) g_negsum[i] = 0.0f;
}

// -------- neg labels: argmax over C of neg_pseudo_logits [B,C,N] --------
__global__ void k_neglabels(const float* __restrict__ npl) {
    int i = blockIdx.x * blockDim.x + threadIdx.x;
    if (i >= B * NN) return;
    int b = i / NN, n = i % NN;
    const float* base = npl + (size_t)b * C * NN + n;
    float best = base[0];
    int bi = 0;
#pragma unroll
    for (int c = 1; c < C; ++c) {
        float v = base[(size_t)c * NN];
        if (v > best) { best = v; bi = c; }
    }
    g_neg_labels[i] = bi;
}

// -------- anchor precompute: pos1, labels1, mask1 --------
__global__ void k_anchor(const float* __restrict__ f1, const float* __restrict__ f2,
                         const float* __restrict__ pl1, const float* __restrict__ pl2) {
    int i = blockIdx.x * blockDim.x + threadIdx.x;
    if (i >= B * P) return;
    int b = i / P, p = i % P;

    const float* a  = f1 + (size_t)b * D * P + p;
    const float* bb = f2 + (size_t)b * D * P + p;
    float s = 0.0f;
#pragma unroll 16
    for (int d = 0; d < D; ++d) s += a[(size_t)d * P] * bb[(size_t)d * P];
    g_pos1[i] = s * 10.0f;   // /TEMP

    const float* q1 = pl1 + (size_t)b * C * P + p;
    const float* q2 = pl2 + (size_t)b * C * P + p;
    float best = q1[0];
    int bi = 0;
    int m = 0;
    bool found = false;
    {
        float v1 = q1[0], v2 = q2[0];
        if (v1 < v2 && v2 > GAMMA) { found = true; m = 0; }
    }
#pragma unroll
    for (int c = 1; c < C; ++c) {
        float v1 = q1[(size_t)c * P], v2 = q2[(size_t)c * P];
        if (v1 > best) { best = v1; bi = c; }
        if (!found && (v1 < v2) && (v2 > GAMMA)) { found = true; m = c; }
    }
    g_labels1[i] = bi;
    g_mask1[i]   = (float)m;   // argmax of 0/1 combo => first hit index, else 0
}

// -------- main: tiled GEMM (64x64, full K=128 in smem) + fused masked-exp epilogue --------
extern __shared__ float smem_dyn[];

__global__ void __launch_bounds__(256, 3)
k_main(const float* __restrict__ f1, const float* __restrict__ neg) {
    float* As = smem_dyn;            // [D][TP]  = 128*64 floats
    float* Bs = smem_dyn + D * TP;   // [D][TN]  = 128*64 floats

    const int b  = blockIdx.z;
    const int p0 = blockIdx.x * TP;
    const int tx = threadIdx.x;      // 0..15 -> 4 n columns
    const int ty = threadIdx.y;      // 0..15 -> 4 p rows
    const int tid = ty * 16 + tx;

    // --- load A tile once (zero-pad p >= P) ---
    const float* f1b = f1 + (size_t)b * D * P;
#pragma unroll
    for (int it = 0; it < 8; ++it) {
        int f4 = tid + it * 256;           // 0..2047 float4 slots (128 rows x 16 f4)
        int d  = f4 >> 4;
        int c4 = (f4 & 15) * 4;
        int p  = p0 + c4;
        float4 v;
        if (p + 3 < P) {
            v = *(const float4*)(f1b + (size_t)d * P + p);
        } else {
            float t0 = (p + 0 < P) ? f1b[(size_t)d * P + p + 0] : 0.0f;
            float t1 = (p + 1 < P) ? f1b[(size_t)d * P + p + 1] : 0.0f;
            float t2 = (p + 2 < P) ? f1b[(size_t)d * P + p + 2] : 0.0f;
            float t3 = (p + 3 < P) ? f1b[(size_t)d * P + p + 3] : 0.0f;
            v = make_float4(t0, t1, t2, t3);
        }
        *(float4*)(As + d * TP + c4) = v;
    }

    int l1[4];
#pragma unroll
    for (int i = 0; i < 4; ++i) {
        int p = p0 + ty * 4 + i;
        l1[i] = (p < P) ? g_labels1[b * P + p] : -1;
    }

    float accN[4] = {0.f, 0.f, 0.f, 0.f};

    const float* negb   = neg + (size_t)b * D * NN;
    const int    n_base = blockIdx.y * NTILES_PER_CHUNK * TN;

    for (int t = 0; t < NTILES_PER_CHUNK; ++t) {
        const int n0 = n_base + t * TN;
        __syncthreads();
#pragma unroll
        for (int it = 0; it < 8; ++it) {
            int f4 = tid + it * 256;
            int d  = f4 >> 4;
            int c4 = (f4 & 15) * 4;
            *(float4*)(Bs + d * TN + c4) =
                *(const float4*)(negb + (size_t)d * NN + n0 + c4);
        }
        __syncthreads();

        float dot[4][4];
#pragma unroll
        for (int i = 0; i < 4; ++i)
#pragma unroll
            for (int j = 0; j < 4; ++j) dot[i][j] = 0.0f;

#pragma unroll 8
        for (int d = 0; d < D; ++d) {
            float4 av = *(const float4*)(As + d * TP + ty * 4);
            float4 bv = *(const float4*)(Bs + d * TN + tx * 4);
            float a0[4] = {av.x, av.y, av.z, av.w};
            float b0[4] = {bv.x, bv.y, bv.z, bv.w};
#pragma unroll
            for (int i = 0; i < 4; ++i)
#pragma unroll
                for (int j = 0; j < 4; ++j)
                    dot[i][j] += a0[i] * b0[j];
        }

        // epilogue: masked exp accumulate over this n-tile
        int4 nl4 = *(const int4*)(g_neg_labels + b * NN + n0 + tx * 4);
        int nlv[4] = {nl4.x, nl4.y, nl4.z, nl4.w};
#pragma unroll
        for (int i = 0; i < 4; ++i) {
            float s = 0.0f;
#pragma unroll
            for (int j = 0; j < 4; ++j) {
                float e = __expf(dot[i][j] * 10.0f);   // MUFU.EX2 path
                if (l1[i] != nlv[j]) s += e;
            }
            accN[i] += s;
        }
    }

    // reduce the 16 tx-threads that share the same 4 p-rows (16-lane segments)
#pragma unroll
    for (int i = 0; i < 4; ++i) {
        float v = accN[i];
#pragma unroll
        for (int off = 8; off > 0; off >>= 1)
            v += __shfl_down_sync(0xffffffffu, v, off, 16);
        if (tx == 0) {
            int p = p0 + ty * 4 + i;
            if (p < P) atomicAdd(&g_negsum[b * P + p], v);
        }
    }
}

// -------- finalize: per-pixel loss, weighted reduction, scalar out --------
__global__ void k_final(float* __restrict__ out) {
    const int tid = threadIdx.x;
    float sl[2] = {0.f, 0.f}, sm[2] = {0.f, 0.f};
    for (int p = tid; p < P; p += blockDim.x) {
#pragma unroll
        for (int b = 0; b < 2; ++b) {
            int i = b * P + p;
            float pe    = expf(g_pos1[i]);
            float ns    = g_negsum[i];
            float lossn = -logf(pe / (pe + ns + EPS) + EPS);
            float m     = g_mask1[i];
            sl[b] += m * lossn;
            sm[b] += m;
        }
    }
    __shared__ float red[4][256];
    red[0][tid] = sl[0]; red[1][tid] = sl[1];
    red[2][tid] = sm[0]; red[3][tid] = sm[1];
    __syncthreads();
    for (int s = 128; s > 0; s >>= 1) {
        if (tid < s) {
#pragma unroll
            for (int k = 0; k < 4; ++k) red[k][tid] += red[k][tid + s];
        }
        __syncthreads();
    }
    if (tid == 0) {
        float l0 = red[0][0] / (red[2][0] + EPS);
        float l1 = red[1][0] / (red[3][0] + EPS);
        out[0] = 0.1f * (l0 + l1);
    }
}

// -------- launch --------
extern "C" void kernel_launch(void* const* d_in, const int* in_sizes, int n_in,
                              void* d_out, int out_size) {
    const float* feats_view1 = (const float*)d_in[0];  // [B,D,240,240]
    const float* pos_feats1  = (const float*)d_in[1];  // [B,D,60,60]
    const float* pos_feats2  = (const float*)d_in[2];  // [B,D,60,60]
    const float* pl1         = (const float*)d_in[3];  // [B,C,60,60]
    const float* pl2         = (const float*)d_in[4];  // [B,C,60,60]
    const float* npl         = (const float*)d_in[5];  // [B,C,240,240]

    const int smem_bytes = (D * TP + D * TN) * sizeof(float);  // 64 KB
    cudaFuncSetAttribute(k_main, cudaFuncAttributeMaxDynamicSharedMemorySize, smem_bytes);

    k_zero<<<(B * P + 255) / 256, 256>>>();
    k_neglabels<<<(B * NN + 255) / 256, 256>>>(npl);
    k_anchor<<<(B * P + 127) / 128, 128>>>(pos_feats1, pos_feats2, pl1, pl2);

    dim3 grid((P + TP - 1) / TP, NSPLIT, B);   // 57 x 4 x 2 = 456 CTAs
    dim3 blk(16, 16);
    k_main<<<grid, blk, smem_bytes>>>(pos_feats1, feats_view1);

    k_final<<<1, 256>>>((float*)d_out);
}

// round 4
// speedup vs baseline: 3.3663x; 3.3663x over previous
#include <cuda_runtime.h>
#include <cuda_bf16.h>
#include <math.h>
#include <stdint.h>

#define B 2
#define D 128
#define P 3600
#define NN 57600
#define C 19
#define GAMMA 0.75f
#define EPS 1e-8f

#define PTILES 29        // ceil(3600/128)
#define NTILES 450       // 57600/128
#define SPLIT 5
#define TPC 90           // n-tiles per CTA

// -------- device global scratch (no allocation allowed) --------
// A fragments: [b][pt][ks 8][mf 8][lane 32][4 u32]  (m16n8k16 A regs)
static __device__ __align__(16) uint32_t g_afr[B * PTILES * 8192];
// B fragments: [b][nt][ks 8][nf 16][lane 32][2 u32] (m16n8k16 B regs)
static __device__ __align__(16) uint32_t g_bfr[B * NTILES * 8192];
static __device__ int   g_neg_labels[B * NN];
static __device__ int   g_labels1[B * P];
static __device__ float g_mask1[B * P];
static __device__ float g_pos1[B * P];
static __device__ float g_negsum[B * P];

// -------- fast exp(10*dot) on the FMA pipe (no MUFU) --------
__device__ __forceinline__ float fexp10(float dot) {
    float t = dot * 14.4269504089f;        // 10 * log2(e)
    float y = t + 12582912.0f;             // 1.5 * 2^23 : round-to-nearest int
    int  ib = __float_as_int(y) << 23;     // i << 23 (low 9 bits of magic are 0)
    float f = t - (y - 12582912.0f);       // f in [-0.5, 0.5]
    float r =            1.3298820e-3f;
    r = fmaf(r, f, 9.6181291e-3f);
    r = fmaf(r, f, 5.5504109e-2f);
    r = fmaf(r, f, 2.4022651e-1f);
    r = fmaf(r, f, 6.9314718e-1f);
    r = fmaf(r, f, 1.0f);
    return __int_as_float(__float_as_int(r) + ib);   // r * 2^i
}

// -------- zero accumulators --------
__global__ void k_zero() {
    int i = blockIdx.x * blockDim.x + threadIdx.x;
    if (i < B * P) g_negsum[i] = 0.0f;
}

// -------- neg labels: argmax over C --------
__global__ void k_neglabels(const float* __restrict__ npl) {
    int i = blockIdx.x * blockDim.x + threadIdx.x;
    if (i >= B * NN) return;
    int b = i / NN, n = i % NN;
    const float* base = npl + (size_t)b * C * NN + n;
    float best = base[0];
    int bi = 0;
#pragma unroll
    for (int c = 1; c < C; ++c) {
        float v = base[(size_t)c * NN];
        if (v > best) { best = v; bi = c; }
    }
    g_neg_labels[i] = bi;
}

// -------- anchor precompute: pos1 (fp32), labels1, mask1 --------
__global__ void k_anchor(const float* __restrict__ f1, const float* __restrict__ f2,
                         const float* __restrict__ pl1, const float* __restrict__ pl2) {
    int i = blockIdx.x * blockDim.x + threadIdx.x;
    if (i >= B * P) return;
    int b = i / P, p = i % P;

    const float* a  = f1 + (size_t)b * D * P + p;
    const float* bb = f2 + (size_t)b * D * P + p;
    float s = 0.0f;
#pragma unroll 16
    for (int d = 0; d < D; ++d) s += a[(size_t)d * P] * bb[(size_t)d * P];
    g_pos1[i] = s * 10.0f;

    const float* q1 = pl1 + (size_t)b * C * P + p;
    const float* q2 = pl2 + (size_t)b * C * P + p;
    float best = q1[0];
    int bi = 0, m = 0;
    bool found = ((q1[0] < q2[0]) && (q2[0] > GAMMA));
#pragma unroll
    for (int c = 1; c < C; ++c) {
        float v1 = q1[(size_t)c * P], v2 = q2[(size_t)c * P];
        if (v1 > best) { best = v1; bi = c; }
        if (!found && (v1 < v2) && (v2 > GAMMA)) { found = true; m = c; }
    }
    g_labels1[i] = bi;
    g_mask1[i]   = (float)m;
}

// -------- pack helpers --------
__device__ __forceinline__ uint32_t pack_bf16x2(float v0, float v1) {
    __nv_bfloat16 h0 = __float2bfloat16_rn(v0);
    __nv_bfloat16 h1 = __float2bfloat16_rn(v1);
    return (uint32_t)(*(uint16_t*)&h0) | ((uint32_t)(*(uint16_t*)&h1) << 16);
}

// -------- convert anchor feats -> bf16 A fragments --------
// layout bits: r[0:1] lane[2:6] mf[7:9] ks[10:12]
__global__ void k_convert_a(const float* __restrict__ f1) {
    int pt = blockIdx.x, b = blockIdx.y;
    const float* src = f1 + (size_t)b * D * P;
    uint32_t* dst = g_afr + (size_t)(b * PTILES + pt) * 8192;
#pragma unroll
    for (int it = 0; it < 32; ++it) {
        int o = threadIdx.x + it * 256;
        int r    = o & 3;
        int lane = (o >> 2) & 31;
        int mf   = (o >> 7) & 7;
        int ks   = o >> 10;
        int row = mf * 16 + (lane >> 2) + (r & 1) * 8;
        int kb  = ks * 16 + (lane & 3) * 2 + (r >> 1) * 8;
        int p   = pt * 128 + row;
        float v0 = 0.f, v1 = 0.f;
        if (p < P) {
            v0 = src[(size_t)kb * P + p];
            v1 = src[(size_t)(kb + 1) * P + p];
        }
        dst[o] = pack_bf16x2(v0, v1);
    }
}

// -------- convert neg feats -> bf16 B fragments --------
// layout bits: r[0] lane[1:5] nf[6:9] ks[10:12]
__global__ void k_convert_neg(const float* __restrict__ neg) {
    int nt = blockIdx.x, b = blockIdx.y;
    const float* src = neg + (size_t)b * D * NN;
    uint32_t* dst = g_bfr + (size_t)(b * NTILES + nt) * 8192;
#pragma unroll
    for (int it = 0; it < 32; ++it) {
        int o = threadIdx.x + it * 256;
        int r    = o & 1;
        int lane = (o >> 1) & 31;
        int nf   = (o >> 6) & 15;
        int ks   = o >> 10;                     // FIXED: was o >> 9 (OOB reads)
        int n  = nt * 128 + nf * 8 + (lane >> 2);
        int kb = ks * 16 + r * 8 + (lane & 3) * 2;
        float v0 = src[(size_t)kb * NN + n];
        float v1 = src[(size_t)(kb + 1) * NN + n];
        dst[o] = pack_bf16x2(v0, v1);
    }
}

// -------- mma.sync wrapper --------
__device__ __forceinline__ void hmma(float* c, const uint32_t* a, const uint32_t* bb) {
    asm volatile(
        "mma.sync.aligned.m16n8k16.row.col.f32.bf16.bf16.f32 "
        "{%0,%1,%2,%3}, {%4,%5,%6,%7}, {%8,%9}, {%0,%1,%2,%3};"
        : "+f"(c[0]), "+f"(c[1]), "+f"(c[2]), "+f"(c[3])
        : "r"(a[0]), "r"(a[1]), "r"(a[2]), "r"(a[3]), "r"(bb[0]), "r"(bb[1]));
}

// -------- main: HMMA GEMM + fused masked poly-exp epilogue --------
__global__ void __launch_bounds__(256, 2) k_main() {
    const int tid  = threadIdx.x;
    const int wid  = tid >> 5;
    const int lane = tid & 31;
    const int pt = blockIdx.x, sp = blockIdx.y, b = blockIdx.z;
    const int warp_m = wid >> 2;   // 0..1 -> 64 rows
    const int warp_n = wid & 3;    // 0..3 -> 32 cols

    // row labels for this thread's accumulator rows (mf 0..3, h 0..1)
    int rl[4][2];
#pragma unroll
    for (int mf = 0; mf < 4; ++mf)
#pragma unroll
        for (int h = 0; h < 2; ++h) {
            int p = pt * 128 + warp_m * 64 + mf * 16 + (lane >> 2) + h * 8;
            rl[mf][h] = (p < P) ? g_labels1[b * P + p] : -1;
        }

    float racc[4][2];
#pragma unroll
    for (int mf = 0; mf < 4; ++mf) { racc[mf][0] = 0.f; racc[mf][1] = 0.f; }

    const uint32_t* afr = g_afr + (size_t)(b * PTILES + pt) * 8192;
    const int tile0 = sp * TPC;

    for (int t = 0; t < TPC; ++t) {
        const int nt = tile0 + t;
        const uint32_t* bfr = g_bfr + (size_t)(b * NTILES + nt) * 8192;

        float c[4][4][4];
#pragma unroll
        for (int mf = 0; mf < 4; ++mf)
#pragma unroll
            for (int nf = 0; nf < 4; ++nf)
#pragma unroll
                for (int k = 0; k < 4; ++k) c[mf][nf][k] = 0.f;

#pragma unroll
        for (int ks = 0; ks < 8; ++ks) {
            uint32_t bregs[4][2];
#pragma unroll
            for (int nf = 0; nf < 4; ++nf) {
                const uint2 v = *(const uint2*)
                    (bfr + (((ks * 16 + warp_n * 4 + nf) * 32 + lane) << 1));
                bregs[nf][0] = v.x; bregs[nf][1] = v.y;
            }
#pragma unroll
            for (int mf = 0; mf < 4; ++mf) {
                uint32_t aregs[4];
                const uint4 v = *(const uint4*)
                    (afr + (((ks * 8 + warp_m * 4 + mf) * 32 + lane) << 2));
                aregs[0] = v.x; aregs[1] = v.y; aregs[2] = v.z; aregs[3] = v.w;
#pragma unroll
                for (int nf = 0; nf < 4; ++nf)
                    hmma(c[mf][nf], aregs, bregs[nf]);
            }
        }

        // epilogue: masked exp accumulate (fma-pipe poly)
        const int* nl = g_neg_labels + b * NN + nt * 128 + warp_n * 32;
#pragma unroll
        for (int nf = 0; nf < 4; ++nf) {
            const int cl0 = nl[nf * 8 + (lane & 3) * 2 + 0];
            const int cl1 = nl[nf * 8 + (lane & 3) * 2 + 1];
#pragma unroll
            for (int mf = 0; mf < 4; ++mf) {
#pragma unroll
                for (int h = 0; h < 2; ++h) {
                    float e0 = fexp10(c[mf][nf][h * 2 + 0]);
                    float e1 = fexp10(c[mf][nf][h * 2 + 1]);
                    if (rl[mf][h] != cl0) racc[mf][h] += e0;
                    if (rl[mf][h] != cl1) racc[mf][h] += e1;
                }
            }
        }
    }

    // reduce across the 4 lanes of each quad (they share rows), then atomadd
#pragma unroll
    for (int mf = 0; mf < 4; ++mf)
#pragma unroll
        for (int h = 0; h < 2; ++h) {
            float v = racc[mf][h];
            v += __shfl_xor_sync(0xffffffffu, v, 1);
            v += __shfl_xor_sync(0xffffffffu, v, 2);
            if ((lane & 3) == 0) {
                int p = pt * 128 + warp_m * 64 + mf * 16 + (lane >> 2) + h * 8;
                if (p < P) atomicAdd(&g_negsum[b * P + p], v);
            }
        }
}

// -------- finalize --------
__global__ void k_final(float* __restrict__ out) {
    const int tid = threadIdx.x;
    float sl[2] = {0.f, 0.f}, sm[2] = {0.f, 0.f};
    for (int p = tid; p < P; p += blockDim.x) {
#pragma unroll
        for (int b = 0; b < 2; ++b) {
            int i = b * P + p;
            float pe    = expf(g_pos1[i]);
            float ns    = g_negsum[i];
            float lossn = -logf(pe / (pe + ns + EPS) + EPS);
            float m     = g_mask1[i];
            sl[b] += m * lossn;
            sm[b] += m;
        }
    }
    __shared__ float red[4][256];
    red[0][tid] = sl[0]; red[1][tid] = sl[1];
    red[2][tid] = sm[0]; red[3][tid] = sm[1];
    __syncthreads();
    for (int s = 128; s > 0; s >>= 1) {
        if (tid < s) {
#pragma unroll
            for (int k = 0; k < 4; ++k) red[k][tid] += red[k][tid + s];
        }
        __syncthreads();
    }
    if (tid == 0) {
        float l0 = red[0][0] / (red[2][0] + EPS);
        float l1 = red[1][0] / (red[3][0] + EPS);
        out[0] = 0.1f * (l0 + l1);
    }
}

// -------- launch --------
extern "C" void kernel_launch(void* const* d_in, const int* in_sizes, int n_in,
                              void* d_out, int out_size) {
    const float* feats_view1 = (const float*)d_in[0];  // [B,D,240,240]
    const float* pos_feats1  = (const float*)d_in[1];  // [B,D,60,60]
    const float* pos_feats2  = (const float*)d_in[2];  // [B,D,60,60]
    const float* pl1         = (const float*)d_in[3];
    const float* pl2         = (const float*)d_in[4];
    const float* npl         = (const float*)d_in[5];  // [B,C,240,240]

    k_zero<<<(B * P + 255) / 256, 256>>>();
    k_neglabels<<<(B * NN + 255) / 256, 256>>>(npl);
    k_anchor<<<(B * P + 127) / 128, 128>>>(pos_feats1, pos_feats2, pl1, pl2);
    k_convert_neg<<<dim3(NTILES, B), 256>>>(feats_view1);
    k_convert_a<<<dim3(PTILES, B), 256>>>(pos_feats1);

    k_main<<<dim3(PTILES, SPLIT, B), 256>>>();

    k_final<<<1, 256>>>((float*)d_out);
}

// round 5
// speedup vs baseline: 4.0396x; 1.2000x over previous
#include <cuda_runtime.h>
#include <cuda_bf16.h>
#include <math.h>
#include <stdint.h>

#define B 2
#define D 128
#define P 3600
#define NN 57600
#define C 19
#define GAMMA 0.75f
#define EPS 1e-8f

#define PTILES 29        // ceil(3600/128)
#define NTILES 450       // 57600/128
#define SPLIT 5
#define TPC 90           // n-tiles per CTA

// -------- device global scratch (no allocation allowed) --------
// A fragments (pre-scaled by 10*log2e): [b][pt][ks 8][mf 8][lane 32][4 u32]
static __device__ __align__(16) uint32_t g_afr[B * PTILES * 8192];
// B fragments, nf-paired uint4: [b][nt][ks 8][nq 8][lane 32][4 u32]
static __device__ __align__(16) uint32_t g_bfr[B * NTILES * 8192];
static __device__ int   g_neg_labels[B * NN];
static __device__ int   g_labels1[B * P];
static __device__ float g_mask1[B * P];
static __device__ float g_pos1[B * P];
static __device__ float g_negsum[B * P];

#define LOG2E10 14.4269504089f   // 10 * log2(e)

// -------- zero accumulators --------
__global__ void k_zero() {
    int i = blockIdx.x * blockDim.x + threadIdx.x;
    if (i < B * P) g_negsum[i] = 0.0f;
}

// -------- neg labels: argmax over C --------
__global__ void k_neglabels(const float* __restrict__ npl) {
    int i = blockIdx.x * blockDim.x + threadIdx.x;
    if (i >= B * NN) return;
    int b = i / NN, n = i % NN;
    const float* base = npl + (size_t)b * C * NN + n;
    float best = base[0];
    int bi = 0;
#pragma unroll
    for (int c = 1; c < C; ++c) {
        float v = base[(size_t)c * NN];
        if (v > best) { best = v; bi = c; }
    }
    g_neg_labels[i] = bi;
}

// -------- anchor precompute: pos1 (fp32), labels1, mask1 --------
__global__ void k_anchor(const float* __restrict__ f1, const float* __restrict__ f2,
                         const float* __restrict__ pl1, const float* __restrict__ pl2) {
    int i = blockIdx.x * blockDim.x + threadIdx.x;
    if (i >= B * P) return;
    int b = i / P, p = i % P;

    const float* a  = f1 + (size_t)b * D * P + p;
    const float* bb = f2 + (size_t)b * D * P + p;
    float s = 0.0f;
#pragma unroll 16
    for (int d = 0; d < D; ++d) s += a[(size_t)d * P] * bb[(size_t)d * P];
    g_pos1[i] = s * 10.0f;

    const float* q1 = pl1 + (size_t)b * C * P + p;
    const float* q2 = pl2 + (size_t)b * C * P + p;
    float best = q1[0];
    int bi = 0, m = 0;
    bool found = ((q1[0] < q2[0]) && (q2[0] > GAMMA));
#pragma unroll
    for (int c = 1; c < C; ++c) {
        float v1 = q1[(size_t)c * P], v2 = q2[(size_t)c * P];
        if (v1 > best) { best = v1; bi = c; }
        if (!found && (v1 < v2) && (v2 > GAMMA)) { found = true; m = c; }
    }
    g_labels1[i] = bi;
    g_mask1[i]   = (float)m;
}

// -------- pack helpers --------
__device__ __forceinline__ uint32_t pack_bf16x2(float v0, float v1) {
    __nv_bfloat16 h0 = __float2bfloat16_rn(v0);
    __nv_bfloat16 h1 = __float2bfloat16_rn(v1);
    return (uint32_t)(*(uint16_t*)&h0) | ((uint32_t)(*(uint16_t*)&h1) << 16);
}

// -------- convert anchor feats -> bf16 A fragments, PRE-SCALED by 10*log2e --------
// layout bits: r[0:1] lane[2:6] mf[7:9] ks[10:12]
__global__ void k_convert_a(const float* __restrict__ f1) {
    int pt = blockIdx.x, b = blockIdx.y;
    const float* src = f1 + (size_t)b * D * P;
    uint32_t* dst = g_afr + (size_t)(b * PTILES + pt) * 8192;
#pragma unroll
    for (int it = 0; it < 32; ++it) {
        int o = threadIdx.x + it * 256;
        int r    = o & 3;
        int lane = (o >> 2) & 31;
        int mf   = (o >> 7) & 7;
        int ks   = o >> 10;
        int row = mf * 16 + (lane >> 2) + (r & 1) * 8;
        int kb  = ks * 16 + (lane & 3) * 2 + (r >> 1) * 8;
        int p   = pt * 128 + row;
        float v0 = 0.f, v1 = 0.f;
        if (p < P) {
            v0 = src[(size_t)kb * P + p] * LOG2E10;
            v1 = src[(size_t)(kb + 1) * P + p] * LOG2E10;
        }
        dst[o] = pack_bf16x2(v0, v1);
    }
}

// -------- convert neg feats -> bf16 B fragments, nf-paired for LDG.128 --------
// u32 layout bits: q[0:1] lane[2:6] nq[7:9] ks[10:12]
// nf = nq*2 + (q>>1), r = q&1
__global__ void k_convert_neg(const float* __restrict__ neg) {
    int nt = blockIdx.x, b = blockIdx.y;
    const float* src = neg + (size_t)b * D * NN;
    uint32_t* dst = g_bfr + (size_t)(b * NTILES + nt) * 8192;
#pragma unroll
    for (int it = 0; it < 32; ++it) {
        int o = threadIdx.x + it * 256;
        int q    = o & 3;
        int lane = (o >> 2) & 31;
        int nq   = (o >> 7) & 7;
        int ks   = o >> 10;
        int nf = nq * 2 + (q >> 1);
        int r  = q & 1;
        int n  = nt * 128 + nf * 8 + (lane >> 2);
        int kb = ks * 16 + r * 8 + (lane & 3) * 2;
        float v0 = src[(size_t)kb * NN + n];
        float v1 = src[(size_t)(kb + 1) * NN + n];
        dst[o] = pack_bf16x2(v0, v1);
    }
}

// -------- mma.sync wrapper --------
__device__ __forceinline__ void hmma(float* c, const uint32_t* a, const uint32_t* bb) {
    asm volatile(
        "mma.sync.aligned.m16n8k16.row.col.f32.bf16.bf16.f32 "
        "{%0,%1,%2,%3}, {%4,%5,%6,%7}, {%8,%9}, {%0,%1,%2,%3};"
        : "+f"(c[0]), "+f"(c[1]), "+f"(c[2]), "+f"(c[3])
        : "r"(a[0]), "r"(a[1]), "r"(a[2]), "r"(a[3]), "r"(bb[0]), "r"(bb[1]));
}

// -------- main: HMMA GEMM (log2 domain) + MUFU.EX2 masked epilogue --------
__global__ void __launch_bounds__(256, 2) k_main() {
    const int tid  = threadIdx.x;
    const int wid  = tid >> 5;
    const int lane = tid & 31;
    const int pt = blockIdx.x, sp = blockIdx.y, b = blockIdx.z;
    const int warp_m = wid >> 2;   // 0..1 -> 64 rows
    const int warp_n = wid & 3;    // 0..3 -> 32 cols

    // row labels for this thread's accumulator rows (mf 0..3, h 0..1)
    int rl[4][2];
#pragma unroll
    for (int mf = 0; mf < 4; ++mf)
#pragma unroll
        for (int h = 0; h < 2; ++h) {
            int p = pt * 128 + warp_m * 64 + mf * 16 + (lane >> 2) + h * 8;
            rl[mf][h] = (p < P) ? g_labels1[b * P + p] : -1;
        }

    float racc[4][2];
#pragma unroll
    for (int mf = 0; mf < 4; ++mf) { racc[mf][0] = 0.f; racc[mf][1] = 0.f; }

    const uint32_t* afr = g_afr + (size_t)(b * PTILES + pt) * 8192;
    const int tile0 = sp * TPC;

    for (int t = 0; t < TPC; ++t) {
        const int nt = tile0 + t;
        const uint32_t* bfr = g_bfr + (size_t)(b * NTILES + nt) * 8192;

        float c[4][4][4];
#pragma unroll
        for (int mf = 0; mf < 4; ++mf)
#pragma unroll
            for (int nf = 0; nf < 4; ++nf)
#pragma unroll
                for (int k = 0; k < 4; ++k) c[mf][nf][k] = 0.f;

#pragma unroll
        for (int ks = 0; ks < 8; ++ks) {
            uint32_t bregs[4][2];
#pragma unroll
            for (int nql = 0; nql < 2; ++nql) {
                const uint4 v = *(const uint4*)
                    (bfr + (((ks * 8 + warp_n * 2 + nql) * 32 + lane) << 2));
                bregs[nql * 2 + 0][0] = v.x; bregs[nql * 2 + 0][1] = v.y;
                bregs[nql * 2 + 1][0] = v.z; bregs[nql * 2 + 1][1] = v.w;
            }
#pragma unroll
            for (int mf = 0; mf < 4; ++mf) {
                uint32_t aregs[4];
                const uint4 v = *(const uint4*)
                    (afr + (((ks * 8 + warp_m * 4 + mf) * 32 + lane) << 2));
                aregs[0] = v.x; aregs[1] = v.y; aregs[2] = v.z; aregs[3] = v.w;
#pragma unroll
                for (int nf = 0; nf < 4; ++nf)
                    hmma(c[mf][nf], aregs, bregs[nf]);
            }
        }

        // epilogue: c is already log2-domain; exp = MUFU.EX2, masked accumulate
        const int* nl = g_neg_labels + b * NN + nt * 128 + warp_n * 32;
#pragma unroll
        for (int nf = 0; nf < 4; ++nf) {
            const int cl0 = nl[nf * 8 + (lane & 3) * 2 + 0];
            const int cl1 = nl[nf * 8 + (lane & 3) * 2 + 1];
#pragma unroll
            for (int mf = 0; mf < 4; ++mf) {
#pragma unroll
                for (int h = 0; h < 2; ++h) {
                    float e0, e1;
                    asm("ex2.approx.f32 %0, %1;" : "=f"(e0) : "f"(c[mf][nf][h * 2 + 0]));
                    asm("ex2.approx.f32 %0, %1;" : "=f"(e1) : "f"(c[mf][nf][h * 2 + 1]));
                    if (rl[mf][h] != cl0) racc[mf][h] += e0;
                    if (rl[mf][h] != cl1) racc[mf][h] += e1;
                }
            }
        }
    }

    // reduce across the 4 lanes of each quad (they share rows), then atomadd
#pragma unroll
    for (int mf = 0; mf < 4; ++mf)
#pragma unroll
        for (int h = 0; h < 2; ++h) {
            float v = racc[mf][h];
            v += __shfl_xor_sync(0xffffffffu, v, 1);
            v += __shfl_xor_sync(0xffffffffu, v, 2);
            if ((lane & 3) == 0) {
                int p = pt * 128 + warp_m * 64 + mf * 16 + (lane >> 2) + h * 8;
                if (p < P) atomicAdd(&g_negsum[b * P + p], v);
            }
        }
}

// -------- finalize --------
__global__ void k_final(float* __restrict__ out) {
    const int tid = threadIdx.x;
    float sl[2] = {0.f, 0.f}, sm[2] = {0.f, 0.f};
    for (int p = tid; p < P; p += blockDim.x) {
#pragma unroll
        for (int b = 0; b < 2; ++b) {
            int i = b * P + p;
            float pe    = expf(g_pos1[i]);
            float ns    = g_negsum[i];
            float lossn = -logf(pe / (pe + ns + EPS) + EPS);
            float m     = g_mask1[i];
            sl[b] += m * lossn;
            sm[b] += m;
        }
    }
    __shared__ float red[4][256];
    red[0][tid] = sl[0]; red[1][tid] = sl[1];
    red[2][tid] = sm[0]; red[3][tid] = sm[1];
    __syncthreads();
    for (int s = 128; s > 0; s >>= 1) {
        if (tid < s) {
#pragma unroll
            for (int k = 0; k < 4; ++k) red[k][tid] += red[k][tid + s];
        }
        __syncthreads();
    }
    if (tid == 0) {
        float l0 = red[0][0] / (red[2][0] + EPS);
        float l1 = red[1][0] / (red[3][0] + EPS);
        out[0] = 0.1f * (l0 + l1);
    }
}

// -------- launch --------
extern "C" void kernel_launch(void* const* d_in, const int* in_sizes, int n_in,
                              void* d_out, int out_size) {
    const float* feats_view1 = (const float*)d_in[0];  // [B,D,240,240]
    const float* pos_feats1  = (const float*)d_in[1];  // [B,D,60,60]
    const float* pos_feats2  = (const float*)d_in[2];  // [B,D,60,60]
    const float* pl1         = (const float*)d_in[3];
    const float* pl2         = (const float*)d_in[4];
    const float* npl         = (const float*)d_in[5];  // [B,C,240,240]

    k_zero<<<(B * P + 255) / 256, 256>>>();
    k_neglabels<<<(B * NN + 255) / 256, 256>>>(npl);
    k_anchor<<<(B * P + 127) / 128, 128>>>(pos_feats1, pos_feats2, pl1, pl2);
    k_convert_neg<<<dim3(NTILES, B), 256>>>(feats_view1);
    k_convert_a<<<dim3(PTILES, B), 256>>>(pos_feats1);

    k_main<<<dim3(PTILES, SPLIT, B), 256>>>();

    k_final<<<1, 256>>>((float*)d_out);
}